// round 3
// baseline (speedup 1.0000x reference)
#include <cuda_runtime.h>
#include <math.h>

// N=20000, NUM_COEF=25, C=H=O=S=64, 2H=128, LMAX=4
#define NTH 128

__device__ __constant__ int c_deg[25] = {
    0, 1,1,1, 2,2,2,2,2, 3,3,3,3,3,3,3, 4,4,4,4,4,4,4,4,4
};
__device__ __constant__ float c_bw[25] = {
    0.f,
    1.f/12.f, 1.f/12.f, 1.f/12.f,
    1.f/20.f, 1.f/20.f, 1.f/20.f, 1.f/20.f, 1.f/20.f,
    1.f/28.f, 1.f/28.f, 1.f/28.f, 1.f/28.f, 1.f/28.f, 1.f/28.f, 1.f/28.f,
    1.f/36.f, 1.f/36.f, 1.f/36.f, 1.f/36.f, 1.f/36.f, 1.f/36.f, 1.f/36.f, 1.f/36.f, 1.f/36.f
};

typedef unsigned long long u64;

__device__ __forceinline__ u64 ffma2(u64 a, u64 b, u64 c) {
    u64 d;
    asm("fma.rn.f32x2 %0, %1, %2, %3;" : "=l"(d) : "l"(a), "l"(b), "l"(c));
    return d;
}
__device__ __forceinline__ u64 dup2(float x) {
    u64 r; asm("mov.b64 %0, {%1, %1};" : "=l"(r) : "f"(x)); return r;
}
__device__ __forceinline__ float2 unpk(u64 v) {
    float2 f; asm("mov.b64 {%0, %1}, %2;" : "=f"(f.x), "=f"(f.y) : "l"(v)); return f;
}
__device__ __forceinline__ float silu_f(float v) {
    return v * (1.f / (1.f + __expf(-v)));
}

// smem floats:
//  sxn 1600 | sh 1600 | sg 64x66=4224 | sg1 64x130=8320 | sg2 64x130=8320
//  stg 1600 | sgat 64 | sred 32   => 25760 floats = 103040 B (2 CTAs/SM)
#define SG_LD  66
#define SGW_LD 130
#define SMEM_FLOATS 25760

__global__ __launch_bounds__(NTH, 2)
void fused_equi(
    const float* __restrict__ x,
    const float* __restrict__ nl0w,
    const float* __restrict__ nl0b,
    const float* __restrict__ affw,
    const float* __restrict__ l1w,
    const float* __restrict__ l1b,
    const float* __restrict__ scw,
    const float* __restrict__ scb,
    const float* __restrict__ gw1,
    const float* __restrict__ gw2,
    const float* __restrict__ gw3,
    const float* __restrict__ l2w,
    const float* __restrict__ l2b,
    const float* __restrict__ tg,
    float* __restrict__ out)
{
    extern __shared__ float smf[];
    float* sxn  = smf;                 // 1600
    float* sh   = sxn + 1600;          // 1600
    float* sg   = sh  + 1600;          // 4224
    float* sg1  = sg  + 4224;          // 8320
    float* sg2  = sg1 + 8320;          // 8320
    float* stg  = sg2 + 8320;          // 1600
    float* sgat = stg + 1600;          // 64
    float* sred = sgat + 64;           // 32

    const int tid = threadIdx.x;
    const long long n = blockIdx.x;
    const float* xin = x + n * 1600;

    // ---- load x and to_grid ----
    for (int i = tid; i < 1600; i += NTH) { sxn[i] = xin[i]; stg[i] = tg[i]; }
    __syncthreads();

    // ---- stats ----
    float s0 = 0.f, q0 = 0.f, fn = 0.f;
    for (int i = tid; i < 1600; i += NTH) {
        float v = sxn[i];
        int m = i >> 6;
        if (m == 0) { s0 += v; q0 += v * v; }
        else        { fn += c_bw[m] * v * v; }
    }
    #pragma unroll
    for (int off = 16; off > 0; off >>= 1) {
        s0 += __shfl_xor_sync(0xffffffffu, s0, off);
        q0 += __shfl_xor_sync(0xffffffffu, q0, off);
        fn += __shfl_xor_sync(0xffffffffu, fn, off);
    }
    const int wid = tid >> 5, lane = tid & 31;
    if (lane == 0) { sred[wid] = s0; sred[4 + wid] = q0; sred[8 + wid] = fn; }
    __syncthreads();
    if (tid == 0) {
        float a = 0.f, b = 0.f, c = 0.f;
        #pragma unroll
        for (int w = 0; w < 4; w++) { a += sred[w]; b += sred[4 + w]; c += sred[8 + w]; }
        float mu  = a * (1.f / 64.f);
        float var = b * (1.f / 64.f) - mu * mu;
        sred[16] = mu;
        sred[17] = rsqrtf(var + 1e-5f);
        sred[18] = rsqrtf(c * (1.f / 64.f) + 1e-5f);
    }
    __syncthreads();
    const float mu = sred[16], rstd = sred[17], inv = sred[18];

    // ---- normalize in place ----
    for (int i = tid; i < 1600; i += NTH) {
        int m = i >> 6, cc = i & 63;
        float v = sxn[i];
        if (m == 0) v = (v - mu) * rstd * nl0w[cc] + nl0b[cc];
        else        v = v * inv * affw[(c_deg[m] - 1) * 64 + cc];
        sxn[i] = v;
    }
    __syncthreads();

    // ---- gating = silu(x0n @ scalar_w + scalar_b) ----
    if (tid < 64) {
        float acc = scb[tid];
        #pragma unroll 8
        for (int i = 0; i < 64; i++) acc += sxn[i] * scw[i * 64 + tid];
        sgat[tid] = silu_f(acc);
    }

    // ---- lin1: h[m,o] = xn[m,:] @ lin1_w[deg[m]] (+b at m=0) ----
    {
        const int j = tid & 63, grp = tid >> 6;   // grp in {0,1}
        for (int l = 0; l < 5; l++) {
            const int base = l * l, cnt = 2 * l + 1;
            bool  bv[5];
            int   rw[5];
            #pragma unroll
            for (int s = 0; s < 5; s++) { rw[s] = base + grp + 2 * s; bv[s] = (grp + 2 * s) < cnt; }
            float acc[5] = {};
            const float* w = l1w + l * 4096 + j;
            #pragma unroll 4
            for (int i = 0; i < 64; i++) {
                float wv = w[i * 64];
                #pragma unroll
                for (int s = 0; s < 5; s++)
                    if (bv[s]) acc[s] += sxn[rw[s] * 64 + i] * wv;
            }
            #pragma unroll
            for (int s = 0; s < 5; s++)
                if (bv[s]) sh[rw[s] * 64 + j] = acc[s] + (rw[s] == 0 ? l1b[j] : 0.f);
        }
    }
    __syncthreads();

    const int ty = tid >> 4, tx = tid & 15;    // ty 0..7 (8 rows each), tx 0..15

    // ---- g[s,c] = sum_m tg[s,m]*h[m,c]  (64x64, k=25), packed cols ----
    {
        u64 acc[8][2] = {};
        for (int m = 0; m < 25; m++) {
            ulonglong2 hv = *reinterpret_cast<const ulonglong2*>(sh + m * 64 + tx * 4);
            #pragma unroll
            for (int r = 0; r < 8; r++) {
                u64 tv = dup2(stg[(ty * 8 + r) * 25 + m]);
                acc[r][0] = ffma2(tv, hv.x, acc[r][0]);
                acc[r][1] = ffma2(tv, hv.y, acc[r][1]);
            }
        }
        #pragma unroll
        for (int r = 0; r < 8; r++) {
            int row = ty * 8 + r;
            *reinterpret_cast<float2*>(sg + row * SG_LD + tx * 4)     = unpk(acc[r][0]);
            *reinterpret_cast<float2*>(sg + row * SG_LD + tx * 4 + 2) = unpk(acc[r][1]);
        }
    }
    __syncthreads();

    // ---- g1 = silu(g @ W1)  (64x128, k=64) ----
    {
        u64 acc[8][4] = {};
        #pragma unroll 4
        for (int k = 0; k < 64; k++) {
            ulonglong2 w0 = *reinterpret_cast<const ulonglong2*>(gw1 + k * 128 + tx * 8);
            ulonglong2 w1 = *reinterpret_cast<const ulonglong2*>(gw1 + k * 128 + tx * 8 + 4);
            #pragma unroll
            for (int r = 0; r < 8; r++) {
                u64 av = dup2(sg[(ty * 8 + r) * SG_LD + k]);
                acc[r][0] = ffma2(av, w0.x, acc[r][0]);
                acc[r][1] = ffma2(av, w0.y, acc[r][1]);
                acc[r][2] = ffma2(av, w1.x, acc[r][2]);
                acc[r][3] = ffma2(av, w1.y, acc[r][3]);
            }
        }
        #pragma unroll
        for (int r = 0; r < 8; r++) {
            int row = ty * 8 + r;
            #pragma unroll
            for (int q = 0; q < 4; q++) {
                float2 f = unpk(acc[r][q]);
                f.x = silu_f(f.x); f.y = silu_f(f.y);
                *reinterpret_cast<float2*>(sg1 + row * SGW_LD + tx * 8 + 2 * q) = f;
            }
        }
    }
    __syncthreads();

    // ---- g2 = silu(g1 @ W2)  (64x128, k=128) ----
    {
        u64 acc[8][4] = {};
        #pragma unroll 4
        for (int k = 0; k < 128; k++) {
            ulonglong2 w0 = *reinterpret_cast<const ulonglong2*>(gw2 + k * 128 + tx * 8);
            ulonglong2 w1 = *reinterpret_cast<const ulonglong2*>(gw2 + k * 128 + tx * 8 + 4);
            #pragma unroll
            for (int r = 0; r < 8; r++) {
                u64 av = dup2(sg1[(ty * 8 + r) * SGW_LD + k]);
                acc[r][0] = ffma2(av, w0.x, acc[r][0]);
                acc[r][1] = ffma2(av, w0.y, acc[r][1]);
                acc[r][2] = ffma2(av, w1.x, acc[r][2]);
                acc[r][3] = ffma2(av, w1.y, acc[r][3]);
            }
        }
        #pragma unroll
        for (int r = 0; r < 8; r++) {
            int row = ty * 8 + r;
            #pragma unroll
            for (int q = 0; q < 4; q++) {
                float2 f = unpk(acc[r][q]);
                f.x = silu_f(f.x); f.y = silu_f(f.y);
                *reinterpret_cast<float2*>(sg2 + row * SGW_LD + tx * 8 + 2 * q) = f;
            }
        }
    }
    __syncthreads();

    // ---- g3 = g2 @ W3  (64x64, k=128) -> into sg ----
    {
        u64 acc[8][2] = {};
        #pragma unroll 4
        for (int k = 0; k < 128; k++) {
            ulonglong2 w = *reinterpret_cast<const ulonglong2*>(gw3 + k * 64 + tx * 4);
            #pragma unroll
            for (int r = 0; r < 8; r++) {
                u64 av = dup2(sg2[(ty * 8 + r) * SGW_LD + k]);
                acc[r][0] = ffma2(av, w.x, acc[r][0]);
                acc[r][1] = ffma2(av, w.y, acc[r][1]);
            }
        }
        #pragma unroll
        for (int r = 0; r < 8; r++) {
            int row = ty * 8 + r;
            *reinterpret_cast<float2*>(sg + row * SG_LD + tx * 4)     = unpk(acc[r][0]);
            *reinterpret_cast<float2*>(sg + row * SG_LD + tx * 4 + 2) = unpk(acc[r][1]);
        }
    }
    __syncthreads();

    // ---- hb[m,c] = sum_s tg[s,m]*g3[s,c], m=1..24 ----
    {
        const int j = tid & 63, grp = tid >> 6;   // rows 1+grp+2s, 12 each
        float acc[12] = {};
        for (int s = 0; s < 64; s++) {
            float gv = sg[s * SG_LD + j];
            #pragma unroll
            for (int r = 0; r < 12; r++)
                acc[r] += stg[s * 25 + 1 + grp + 2 * r] * gv;
        }
        #pragma unroll
        for (int r = 0; r < 12; r++) sh[(1 + grp + 2 * r) * 64 + j] = acc[r];
    }
    if (tid < 64) sh[tid] = sgat[tid];
    __syncthreads();

    // ---- lin2: out[m,o] = h_final[m,:] @ lin2_w[deg[m]] (+b at m=0) ----
    {
        const int j = tid & 63, grp = tid >> 6;
        float* outn = out + n * 1600;
        for (int l = 0; l < 5; l++) {
            const int base = l * l, cnt = 2 * l + 1;
            bool  bv[5];
            int   rw[5];
            #pragma unroll
            for (int s = 0; s < 5; s++) { rw[s] = base + grp + 2 * s; bv[s] = (grp + 2 * s) < cnt; }
            float acc[5] = {};
            const float* w = l2w + l * 4096 + j;
            #pragma unroll 4
            for (int i = 0; i < 64; i++) {
                float wv = w[i * 64];
                #pragma unroll
                for (int s = 0; s < 5; s++)
                    if (bv[s]) acc[s] += sh[rw[s] * 64 + i] * wv;
            }
            #pragma unroll
            for (int s = 0; s < 5; s++)
                if (bv[s]) outn[rw[s] * 64 + j] = acc[s] + (rw[s] == 0 ? l2b[j] : 0.f);
        }
    }
}

extern "C" void kernel_launch(void* const* d_in, const int* in_sizes, int n_in,
                              void* d_out, int out_size)
{
    const float* x    = (const float*)d_in[0];
    const float* nl0w = (const float*)d_in[1];
    const float* nl0b = (const float*)d_in[2];
    const float* affw = (const float*)d_in[3];
    const float* l1w  = (const float*)d_in[4];
    const float* l1b  = (const float*)d_in[5];
    const float* scw  = (const float*)d_in[6];
    const float* scb  = (const float*)d_in[7];
    const float* gw1  = (const float*)d_in[8];
    const float* gw2  = (const float*)d_in[9];
    const float* gw3  = (const float*)d_in[10];
    const float* l2w  = (const float*)d_in[11];
    const float* l2b  = (const float*)d_in[12];
    const float* tg   = (const float*)d_in[13];
    float* out = (float*)d_out;

    const int N = in_sizes[0] / 1600;
    const size_t smem = SMEM_FLOATS * sizeof(float);

    cudaFuncSetAttribute(fused_equi, cudaFuncAttributeMaxDynamicSharedMemorySize, (int)smem);
    fused_equi<<<N, NTH, smem>>>(x, nl0w, nl0b, affw, l1w, l1b, scw, scb,
                                 gw1, gw2, gw3, l2w, l2b, tg, out);
}

// round 5
// speedup vs baseline: 1.0185x; 1.0185x over previous
#include <cuda_runtime.h>
#include <math.h>

// N=20000, NUM_COEF=25, C=H=O=S=64, 2H=128, LMAX=4
#define NTH 256

__device__ __constant__ int c_deg[25] = {
    0, 1,1,1, 2,2,2,2,2, 3,3,3,3,3,3,3, 4,4,4,4,4,4,4,4,4
};
__device__ __constant__ float c_bw[25] = {
    0.f,
    1.f/12.f, 1.f/12.f, 1.f/12.f,
    1.f/20.f, 1.f/20.f, 1.f/20.f, 1.f/20.f, 1.f/20.f,
    1.f/28.f, 1.f/28.f, 1.f/28.f, 1.f/28.f, 1.f/28.f, 1.f/28.f, 1.f/28.f,
    1.f/36.f, 1.f/36.f, 1.f/36.f, 1.f/36.f, 1.f/36.f, 1.f/36.f, 1.f/36.f, 1.f/36.f, 1.f/36.f
};

typedef unsigned long long u64;

__device__ __forceinline__ u64 ffma2(u64 a, u64 b, u64 c) {
    u64 d;
    asm("fma.rn.f32x2 %0, %1, %2, %3;" : "=l"(d) : "l"(a), "l"(b), "l"(c));
    return d;
}
__device__ __forceinline__ u64 dup2(float x) {
    u64 r; asm("mov.b64 %0, {%1, %1};" : "=l"(r) : "f"(x)); return r;
}
__device__ __forceinline__ float2 unpk(u64 v) {
    float2 f; asm("mov.b64 {%0, %1}, %2;" : "=f"(f.x), "=f"(f.y) : "l"(v)); return f;
}
__device__ __forceinline__ float silu_f(float v) {
    return v * (1.f / (1.f + __expf(-v)));
}

// smem floats:
//  sxn 1600 (later HB) | sh 1600 | sg 64x66=4224 (later g3) | sg1 64x130=8320
//  sg2 64x130=8320 | stg 1600 | sgat 64 | sred 32  => 25760 fl = 103040 B (2 CTAs/SM)
#define SG_LD  66
#define SGW_LD 130
#define SMEM_FLOATS 25760

__global__ __launch_bounds__(NTH, 2)
void fused_equi(
    const float* __restrict__ x,
    const float* __restrict__ nl0w,
    const float* __restrict__ nl0b,
    const float* __restrict__ affw,
    const float* __restrict__ l1w,
    const float* __restrict__ l1b,
    const float* __restrict__ scw,
    const float* __restrict__ scb,
    const float* __restrict__ gw1,
    const float* __restrict__ gw2,
    const float* __restrict__ gw3,
    const float* __restrict__ l2w,
    const float* __restrict__ l2b,
    const float* __restrict__ tg,
    float* __restrict__ out)
{
    extern __shared__ float smf[];
    float* sxn  = smf;                 // 1600 (aliased by HB later)
    float* sh   = sxn + 1600;          // 1600
    float* sg   = sh  + 1600;          // 4224 (aliased by g3 later)
    float* sg1  = sg  + 4224;          // 8320
    float* sg2  = sg1 + 8320;          // 8320
    float* stg  = sg2 + 8320;          // 1600
    float* sgat = stg + 1600;          // 64
    float* sred = sgat + 64;           // 32

    const int tid = threadIdx.x;
    const long long n = blockIdx.x;
    const float* xin = x + n * 1600;

    // ---- load x and to_grid ----
    for (int i = tid; i < 1600; i += NTH) { sxn[i] = xin[i]; stg[i] = tg[i]; }
    __syncthreads();

    // ---- stats ----
    float s0 = 0.f, q0 = 0.f, fn = 0.f;
    for (int i = tid; i < 1600; i += NTH) {
        float v = sxn[i];
        int m = i >> 6;
        if (m == 0) { s0 += v; q0 += v * v; }
        else        { fn += c_bw[m] * v * v; }
    }
    #pragma unroll
    for (int off = 16; off > 0; off >>= 1) {
        s0 += __shfl_xor_sync(0xffffffffu, s0, off);
        q0 += __shfl_xor_sync(0xffffffffu, q0, off);
        fn += __shfl_xor_sync(0xffffffffu, fn, off);
    }
    const int wid = tid >> 5, lane = tid & 31;
    if (lane == 0) { sred[wid] = s0; sred[8 + wid] = q0; sred[16 + wid] = fn; }
    __syncthreads();
    if (tid == 0) {
        float a = 0.f, b = 0.f, c = 0.f;
        #pragma unroll
        for (int w = 0; w < 8; w++) { a += sred[w]; b += sred[8 + w]; c += sred[16 + w]; }
        float mu  = a * (1.f / 64.f);
        float var = b * (1.f / 64.f) - mu * mu;
        sred[24] = mu;
        sred[25] = rsqrtf(var + 1e-5f);
        sred[26] = rsqrtf(c * (1.f / 64.f) + 1e-5f);
    }
    __syncthreads();
    const float mu = sred[24], rstd = sred[25], inv = sred[26];

    // ---- normalize in place ----
    for (int i = tid; i < 1600; i += NTH) {
        int m = i >> 6, cc = i & 63;
        float v = sxn[i];
        if (m == 0) v = (v - mu) * rstd * nl0w[cc] + nl0b[cc];
        else        v = v * inv * affw[(c_deg[m] - 1) * 64 + cc];
        sxn[i] = v;
    }
    __syncthreads();

    // ---- gating = silu(x0n @ scalar_w + scalar_b) ----
    if (tid < 64) {
        float acc = scb[tid];
        #pragma unroll 8
        for (int i = 0; i < 64; i++) acc += sxn[i] * scw[i * 64 + tid];
        sgat[tid] = silu_f(acc);
    }

    // ---- lin1: h[m,:] = xn[m,:] @ lin1_w[deg[m]] (+b at m=0), f32x2 over col pairs ----
    {
        const int j2 = tid & 31, grp = tid >> 5;   // 32 col-pairs x 8 row groups
        for (int l = 0; l < 5; l++) {
            const int base = l * l, cnt = 2 * l + 1;
            const int r0 = base + grp, r1 = base + grp + 8;
            const bool b0 = grp < cnt, b1 = grp + 8 < cnt;
            u64 a0 = 0, a1 = 0;
            const float* w = l1w + l * 4096 + j2 * 2;
            #pragma unroll 4
            for (int i = 0; i < 64; i++) {
                u64 wv = *reinterpret_cast<const u64*>(w + i * 64);
                if (b0) a0 = ffma2(dup2(sxn[r0 * 64 + i]), wv, a0);
                if (b1) a1 = ffma2(dup2(sxn[r1 * 64 + i]), wv, a1);
            }
            if (b0) {
                float2 f = unpk(a0);
                if (r0 == 0) { f.x += l1b[j2 * 2]; f.y += l1b[j2 * 2 + 1]; }
                *reinterpret_cast<float2*>(sh + r0 * 64 + j2 * 2) = f;
            }
            if (b1) *reinterpret_cast<float2*>(sh + r1 * 64 + j2 * 2) = unpk(a1);
        }
    }
    __syncthreads();

    const int ty = tid >> 4, tx = tid & 15;    // ty 0..15 (4 rows each), tx 0..15

    // ---- to_grid: g[s,c] = sum_m tg[s,m]*h[m,c]  (64x64, k=25) ----
    {
        u64 acc[4][2] = {};
        for (int m = 0; m < 25; m++) {
            ulonglong2 hv = *reinterpret_cast<const ulonglong2*>(sh + m * 64 + tx * 4);
            #pragma unroll
            for (int r = 0; r < 4; r++) {
                u64 tv = dup2(stg[(ty * 4 + r) * 25 + m]);
                acc[r][0] = ffma2(tv, hv.x, acc[r][0]);
                acc[r][1] = ffma2(tv, hv.y, acc[r][1]);
            }
        }
        #pragma unroll
        for (int r = 0; r < 4; r++) {
            int row = ty * 4 + r;
            *reinterpret_cast<float2*>(sg + row * SG_LD + tx * 4)     = unpk(acc[r][0]);
            *reinterpret_cast<float2*>(sg + row * SG_LD + tx * 4 + 2) = unpk(acc[r][1]);
        }
    }
    __syncthreads();

    // ---- g1 = silu(g @ W1)  (64x128, k=64) ----
    {
        u64 acc[4][4] = {};
        #pragma unroll 4
        for (int k = 0; k < 64; k++) {
            ulonglong2 w0 = *reinterpret_cast<const ulonglong2*>(gw1 + k * 128 + tx * 8);
            ulonglong2 w1 = *reinterpret_cast<const ulonglong2*>(gw1 + k * 128 + tx * 8 + 4);
            #pragma unroll
            for (int r = 0; r < 4; r++) {
                u64 av = dup2(sg[(ty * 4 + r) * SG_LD + k]);
                acc[r][0] = ffma2(av, w0.x, acc[r][0]);
                acc[r][1] = ffma2(av, w0.y, acc[r][1]);
                acc[r][2] = ffma2(av, w1.x, acc[r][2]);
                acc[r][3] = ffma2(av, w1.y, acc[r][3]);
            }
        }
        #pragma unroll
        for (int r = 0; r < 4; r++) {
            int row = ty * 4 + r;
            #pragma unroll
            for (int q = 0; q < 4; q++) {
                float2 f = unpk(acc[r][q]);
                f.x = silu_f(f.x); f.y = silu_f(f.y);
                *reinterpret_cast<float2*>(sg1 + row * SGW_LD + tx * 8 + 2 * q) = f;
            }
        }
    }
    __syncthreads();

    // ---- g2 = silu(g1 @ W2)  (64x128, k=128) ----
    {
        u64 acc[4][4] = {};
        #pragma unroll 4
        for (int k = 0; k < 128; k++) {
            ulonglong2 w0 = *reinterpret_cast<const ulonglong2*>(gw2 + k * 128 + tx * 8);
            ulonglong2 w1 = *reinterpret_cast<const ulonglong2*>(gw2 + k * 128 + tx * 8 + 4);
            #pragma unroll
            for (int r = 0; r < 4; r++) {
                u64 av = dup2(sg1[(ty * 4 + r) * SGW_LD + k]);
                acc[r][0] = ffma2(av, w0.x, acc[r][0]);
                acc[r][1] = ffma2(av, w0.y, acc[r][1]);
                acc[r][2] = ffma2(av, w1.x, acc[r][2]);
                acc[r][3] = ffma2(av, w1.y, acc[r][3]);
            }
        }
        #pragma unroll
        for (int r = 0; r < 4; r++) {
            int row = ty * 4 + r;
            #pragma unroll
            for (int q = 0; q < 4; q++) {
                float2 f = unpk(acc[r][q]);
                f.x = silu_f(f.x); f.y = silu_f(f.y);
                *reinterpret_cast<float2*>(sg2 + row * SGW_LD + tx * 8 + 2 * q) = f;
            }
        }
    }
    __syncthreads();

    // ---- g3 = g2 @ W3  (64x64, k=128) -> into sg ----
    {
        u64 acc[4][2] = {};
        #pragma unroll 4
        for (int k = 0; k < 128; k++) {
            ulonglong2 w = *reinterpret_cast<const ulonglong2*>(gw3 + k * 64 + tx * 4);
            #pragma unroll
            for (int r = 0; r < 4; r++) {
                u64 av = dup2(sg2[(ty * 4 + r) * SGW_LD + k]);
                acc[r][0] = ffma2(av, w.x, acc[r][0]);
                acc[r][1] = ffma2(av, w.y, acc[r][1]);
            }
        }
        #pragma unroll
        for (int r = 0; r < 4; r++) {
            int row = ty * 4 + r;
            *reinterpret_cast<float2*>(sg + row * SG_LD + tx * 4)     = unpk(acc[r][0]);
            *reinterpret_cast<float2*>(sg + row * SG_LD + tx * 4 + 2) = unpk(acc[r][1]);
        }
    }
    __syncthreads();

    // ---- from_grid: hb[m,c] = sum_s tg[s,m]*g3[s,c], m=1..24; row0 <- gating ----
    // HB aliases sxn (dead). f32x2 over col pairs.
    {
        const int j2 = tid & 31, grp = tid >> 5;   // rows 1+grp+8r, r<3
        u64 acc[3] = {};
        for (int s = 0; s < 64; s++) {
            u64 gv = *reinterpret_cast<const u64*>(sg + s * SG_LD + j2 * 2);
            #pragma unroll
            for (int r = 0; r < 3; r++)
                acc[r] = ffma2(dup2(stg[s * 25 + 1 + grp + 8 * r]), gv, acc[r]);
        }
        #pragma unroll
        for (int r = 0; r < 3; r++)
            *reinterpret_cast<float2*>(sxn + (1 + grp + 8 * r) * 64 + j2 * 2) = unpk(acc[r]);
    }
    if (tid < 64) sxn[tid] = sgat[tid];
    __syncthreads();

    // ---- lin2: out[m,:] = hb[m,:] @ lin2_w[deg[m]] (+b at m=0) ----
    {
        const int j2 = tid & 31, grp = tid >> 5;
        float* outn = out + n * 1600;
        for (int l = 0; l < 5; l++) {
            const int base = l * l, cnt = 2 * l + 1;
            const int r0 = base + grp, r1 = base + grp + 8;
            const bool b0 = grp < cnt, b1 = grp + 8 < cnt;
            u64 a0 = 0, a1 = 0;
            const float* w = l2w + l * 4096 + j2 * 2;
            #pragma unroll 4
            for (int i = 0; i < 64; i++) {
                u64 wv = *reinterpret_cast<const u64*>(w + i * 64);
                if (b0) a0 = ffma2(dup2(sxn[r0 * 64 + i]), wv, a0);
                if (b1) a1 = ffma2(dup2(sxn[r1 * 64 + i]), wv, a1);
            }
            if (b0) {
                float2 f = unpk(a0);
                if (r0 == 0) { f.x += l2b[j2 * 2]; f.y += l2b[j2 * 2 + 1]; }
                *reinterpret_cast<float2*>(outn + r0 * 64 + j2 * 2) = f;
            }
            if (b1) *reinterpret_cast<float2*>(outn + r1 * 64 + j2 * 2) = unpk(a1);
        }
    }
}

extern "C" void kernel_launch(void* const* d_in, const int* in_sizes, int n_in,
                              void* d_out, int out_size)
{
    const float* x    = (const float*)d_in[0];
    const float* nl0w = (const float*)d_in[1];
    const float* nl0b = (const float*)d_in[2];
    const float* affw = (const float*)d_in[3];
    const float* l1w  = (const float*)d_in[4];
    const float* l1b  = (const float*)d_in[5];
    const float* scw  = (const float*)d_in[6];
    const float* scb  = (const float*)d_in[7];
    const float* gw1  = (const float*)d_in[8];
    const float* gw2  = (const float*)d_in[9];
    const float* gw3  = (const float*)d_in[10];
    const float* l2w  = (const float*)d_in[11];
    const float* l2b  = (const float*)d_in[12];
    const float* tg   = (const float*)d_in[13];
    float* out = (float*)d_out;

    const int N = in_sizes[0] / 1600;
    const size_t smem = SMEM_FLOATS * sizeof(float);

    cudaFuncSetAttribute(fused_equi, cudaFuncAttributeMaxDynamicSharedMemorySize, (int)smem);
    fused_equi<<<N, NTH, smem>>>(x, nl0w, nl0b, affw, l1w, l1b, scw, scb,
                                 gw1, gw2, gw3, l2w, l2b, tg, out);
}